// round 1
// baseline (speedup 1.0000x reference)
#include <cuda_runtime.h>
#include <cstdint>

#define N_NODES 100000
#define E_EDGES 640000
#define D_NODE  256
#define D_EDGE  128
#define D_OUT   128

// Scratch: xw = x @ weight_node  [N, 128]  (51.2 MB, __device__ global = allowed)
__device__ float g_xw[(size_t)N_NODES * D_OUT];
__device__ int   g_idx64;   // 1 if edge_index is int64, 0 if int32

// ---------------------------------------------------------------------------
// Detect edge_index dtype. int32 data reinterpreted as u64 packs two indices:
// value = lo + hi*2^32 >= 2^32 unless hi==0 (prob 1e-5). 64 probes decide.
// ---------------------------------------------------------------------------
__global__ void detect_idx_kernel(const void* __restrict__ eidx) {
    if (threadIdx.x == 0 && blockIdx.x == 0) {
        const unsigned long long* p = (const unsigned long long*)eidx;
        int ok = 1;
        #pragma unroll 1
        for (int i = 0; i < 64; i++) {
            if (p[i] >= (unsigned long long)N_NODES) { ok = 0; break; }
        }
        g_idx64 = ok;
    }
}

__device__ __forceinline__ long ld_idx(const void* __restrict__ p, long i) {
    if (g_idx64) return (long)((const long long*)p)[i];
    return (long)((const int*)p)[i];
}

// ---------------------------------------------------------------------------
// Zero the axw output region (it is accumulated via atomics).
// ---------------------------------------------------------------------------
__global__ void zero_kernel(float* __restrict__ p, long n) {
    long i = (long)blockIdx.x * blockDim.x + threadIdx.x;
    if (i < n) p[i] = 0.0f;
}

// ---------------------------------------------------------------------------
// fp32 tiled GEMM: C[M x 128] = A[M x K] @ B[K x 128], row-major.
// BM=128, BN=128, BK=8, 256 threads, 8x8 register tile per thread.
// ---------------------------------------------------------------------------
#define BM 128
#define BN 128
#define BKK 8
#define TM 8
#define TN 8

__global__ __launch_bounds__(256, 2)
void gemm_f32_kernel(const float* __restrict__ A, const float* __restrict__ B,
                     float* __restrict__ C, int M, int K) {
    __shared__ float As[BKK][BM];
    __shared__ float Bs[BKK][BN];

    const int block_row = blockIdx.x * BM;
    const int tid = threadIdx.x;
    const int tx = tid & 15;       // 0..15 -> col group
    const int ty = tid >> 4;       // 0..15 -> row group

    float acc[TM][TN];
    #pragma unroll
    for (int i = 0; i < TM; i++)
        #pragma unroll
        for (int j = 0; j < TN; j++) acc[i][j] = 0.0f;

    // global-load assignments
    const int a_row = tid >> 1;          // 0..127
    const int a_kq  = (tid & 1) * 4;     // 0 or 4
    const int b_row = tid >> 5;          // 0..7
    const int b_col = (tid & 31) * 4;    // 0..124

    const int gr_a = block_row + a_row;
    const bool a_valid = (gr_a < M);
    const float* a_src = A + (long)gr_a * K + a_kq;

    for (int k0 = 0; k0 < K; k0 += BKK) {
        float4 av = make_float4(0.f, 0.f, 0.f, 0.f);
        if (a_valid) av = *(const float4*)(a_src + k0);
        As[a_kq + 0][a_row] = av.x;
        As[a_kq + 1][a_row] = av.y;
        As[a_kq + 2][a_row] = av.z;
        As[a_kq + 3][a_row] = av.w;

        float4 bv = *(const float4*)&B[(long)(k0 + b_row) * BN + b_col];
        *(float4*)&Bs[b_row][b_col] = bv;

        __syncthreads();

        #pragma unroll
        for (int k = 0; k < BKK; k++) {
            float ar[TM], br[TN];
            #pragma unroll
            for (int i = 0; i < TM; i += 4)
                *(float4*)&ar[i] = *(const float4*)&As[k][ty * TM + i];
            #pragma unroll
            for (int j = 0; j < TN; j += 4)
                *(float4*)&br[j] = *(const float4*)&Bs[k][tx * TN + j];
            #pragma unroll
            for (int i = 0; i < TM; i++)
                #pragma unroll
                for (int j = 0; j < TN; j++)
                    acc[i][j] = fmaf(ar[i], br[j], acc[i][j]);
        }
        __syncthreads();
    }

    #pragma unroll
    for (int i = 0; i < TM; i++) {
        int gr = block_row + ty * TM + i;
        if (gr < M) {
            float4* cp = (float4*)&C[(long)gr * BN + tx * TN];
            cp[0] = make_float4(acc[i][0], acc[i][1], acc[i][2], acc[i][3]);
            cp[1] = make_float4(acc[i][4], acc[i][5], acc[i][6], acc[i][7]);
        }
    }
}

// ---------------------------------------------------------------------------
// Scatter-add: axw[dst] += xw[src]  for every edge. One thread per (edge, 4col).
// ---------------------------------------------------------------------------
__global__ void scatter_kernel(const void* __restrict__ eidx,
                               const float* __restrict__ xw,
                               float* __restrict__ axw) {
    long t = (long)blockIdx.x * blockDim.x + threadIdx.x;
    if (t >= (long)E_EDGES * 32) return;
    long e = t >> 5;
    int  q = (int)(t & 31) * 4;
    long src = ld_idx(eidx, e);
    long dst = ld_idx(eidx, (long)E_EDGES + e);
    float4 v = *(const float4*)&xw[src * D_OUT + q];
    float* o = &axw[dst * D_OUT + q];
    atomicAdd(o + 0, v.x);
    atomicAdd(o + 1, v.y);
    atomicAdd(o + 2, v.z);
    atomicAdd(o + 3, v.w);
}

// ---------------------------------------------------------------------------
// Scores: warp per edge. s = sum_d axw[src][d]*ew[e][d]*axw[dst][d];
// out = s * tc[e] * lw[0]
// ---------------------------------------------------------------------------
__global__ __launch_bounds__(256)
void scores_kernel(const void* __restrict__ eidx,
                   const float* __restrict__ axw,
                   const float* __restrict__ ew,
                   const float* __restrict__ tc,
                   const float* __restrict__ lw,
                   float* __restrict__ scores) {
    long gw = ((long)blockIdx.x * blockDim.x + threadIdx.x) >> 5;
    int lane = threadIdx.x & 31;
    if (gw >= E_EDGES) return;
    long src = ld_idx(eidx, gw);
    long dst = ld_idx(eidx, (long)E_EDGES + gw);
    const float* h = &axw[src * D_OUT];
    const float* t = &axw[dst * D_OUT];
    const float* w = &ew[gw * D_OUT];
    float s = 0.0f;
    #pragma unroll
    for (int c = 0; c < D_OUT; c += 32) {
        int idx = c + lane;
        s = fmaf(h[idx] * w[idx], t[idx], s);
    }
    #pragma unroll
    for (int o = 16; o > 0; o >>= 1)
        s += __shfl_xor_sync(0xFFFFFFFFu, s, o);
    if (lane == 0) scores[gw] = s * tc[gw] * lw[0];
}

// ---------------------------------------------------------------------------
// Launch
// ---------------------------------------------------------------------------
extern "C" void kernel_launch(void* const* d_in, const int* in_sizes, int n_in,
                              void* d_out, int out_size) {
    const float* x    = (const float*)d_in[0];   // [N, 256]
    const float* ea   = (const float*)d_in[1];   // [E, 128]
    const float* tc   = (const float*)d_in[2];   // [E]
    const float* wn   = (const float*)d_in[3];   // [256, 128]
    const float* we   = (const float*)d_in[4];   // [128, 128]
    const float* lw   = (const float*)d_in[5];   // [1]
    const void*  eidx = d_in[6];                 // [2, E] int32 or int64

    float* out    = (float*)d_out;
    float* axw    = out;                                   // [N, 128]
    float* ew     = out + (long)N_NODES * D_OUT;           // [E, 128]
    float* scores = ew  + (long)E_EDGES * D_OUT;           // [E]

    float* xw;
    cudaGetSymbolAddress((void**)&xw, g_xw);

    // 1) dtype detection for edge_index
    detect_idx_kernel<<<1, 32>>>(eidx);

    // 2) zero axw output region (accumulated by atomics)
    {
        long n = (long)N_NODES * D_OUT;
        int blocks = (int)((n + 255) / 256);
        zero_kernel<<<blocks, 256>>>(axw, n);
    }

    // 3) xw = x @ weight_node   [100000 x 256] @ [256 x 128]
    gemm_f32_kernel<<<(N_NODES + BM - 1) / BM, 256>>>(x, wn, xw, N_NODES, D_NODE);

    // 4) axw = segment_sum(xw[src], dst)
    {
        long total = (long)E_EDGES * 32;
        int blocks = (int)((total + 255) / 256);
        scatter_kernel<<<blocks, 256>>>(eidx, xw, axw);
    }

    // 5) ew = edge_attr @ weight_edge   [640000 x 128] @ [128 x 128]
    gemm_f32_kernel<<<(E_EDGES + BM - 1) / BM, 256>>>(ea, we, ew, E_EDGES, D_EDGE);

    // 6) DistMult scores
    {
        long warps = E_EDGES;
        int blocks = (int)((warps * 32 + 255) / 256);
        scores_kernel<<<blocks, 256>>>(eidx, axw, ew, tc, lw, scores);
    }
}

// round 3
// speedup vs baseline: 1.9524x; 1.9524x over previous
#include <cuda_runtime.h>
#include <cuda_bf16.h>
#include <cstdint>

#define N_NODES 100000
#define E_EDGES 640000

// ---------------------------------------------------------------------------
// Global scratch (allocation-free rule: __device__ arrays)
// ---------------------------------------------------------------------------
__device__ float g_xw[(size_t)N_NODES * 128];   // x @ Wn
__device__ int   g_idx64;                        // edge_index dtype flag

// ---------------------------------------------------------------------------
// Helpers
// ---------------------------------------------------------------------------
__device__ __forceinline__ uint32_t smem_u32(const void* p) {
    uint32_t a;
    asm("{ .reg .u64 t; cvta.to.shared.u64 t, %1; cvt.u32.u64 %0, t; }"
        : "=r"(a) : "l"(p));
    return a;
}

__device__ __forceinline__ void mma_bf16(float* d, const uint32_t* a, const uint32_t* b) {
    asm volatile(
        "mma.sync.aligned.m16n8k16.row.col.f32.bf16.bf16.f32 "
        "{%0,%1,%2,%3}, {%4,%5,%6,%7}, {%8,%9}, {%0,%1,%2,%3};"
        : "+f"(d[0]), "+f"(d[1]), "+f"(d[2]), "+f"(d[3])
        : "r"(a[0]), "r"(a[1]), "r"(a[2]), "r"(a[3]), "r"(b[0]), "r"(b[1]));
}

__device__ __forceinline__ void ldsm_x4(uint32_t* r, uint32_t addr) {
    asm volatile("ldmatrix.sync.aligned.m8n8.x4.shared.b16 {%0,%1,%2,%3}, [%4];"
                 : "=r"(r[0]), "=r"(r[1]), "=r"(r[2]), "=r"(r[3]) : "r"(addr));
}
__device__ __forceinline__ void ldsm_x4t(uint32_t* r, uint32_t addr) {
    asm volatile("ldmatrix.sync.aligned.m8n8.x4.trans.shared.b16 {%0,%1,%2,%3}, [%4];"
                 : "=r"(r[0]), "=r"(r[1]), "=r"(r[2]), "=r"(r[3]) : "r"(addr));
}

// ---------------------------------------------------------------------------
// edge_index dtype detection (int32 vs int64)
// ---------------------------------------------------------------------------
__global__ void detect_idx_kernel(const void* __restrict__ eidx) {
    if (threadIdx.x == 0 && blockIdx.x == 0) {
        const unsigned long long* p = (const unsigned long long*)eidx;
        int ok = 1;
        #pragma unroll 1
        for (int i = 0; i < 64; i++)
            if (p[i] >= (unsigned long long)N_NODES) { ok = 0; break; }
        g_idx64 = ok;
    }
}

__device__ __forceinline__ long ld_idx(const void* __restrict__ p, long i) {
    if (g_idx64) return (long)((const long long*)p)[i];
    return (long)((const int*)p)[i];
}

__global__ void zero4_kernel(float4* __restrict__ p, int n4) {
    int i = blockIdx.x * blockDim.x + threadIdx.x;
    if (i < n4) p[i] = make_float4(0.f, 0.f, 0.f, 0.f);
}

// ---------------------------------------------------------------------------
// Persistent bf16x3 mma.sync GEMM: C[M x 128] = A[M x K] @ W[K x 128]
// FUSE: DistMult scores computed in the epilogue from accumulator fragments.
//
// Block = 256 threads = 8 warps in a 4(row) x 2(col) grid; warp tile 32x64.
// Smem: W hi/lo [K x 128] bf16 swizzled, A-chunk hi/lo [128 x 128] bf16
// swizzled, + 1KB reduction buffer. A chunks are register-prefetched so the
// LDGs of tile t+1 overlap the HMMA of tile t.
// ---------------------------------------------------------------------------
template<int KCH, bool FUSE>
__global__ __launch_bounds__(256, 1)
void gemm_mma_kernel(const float* __restrict__ A, const float* __restrict__ W,
                     float* __restrict__ C, int M,
                     const void* __restrict__ eidx,
                     const float* __restrict__ axw,
                     const float* __restrict__ tcl,
                     const float* __restrict__ lw,
                     float* __restrict__ scores) {
    constexpr int K = KCH * 128;
    constexpr uint32_t OFF_B_LO = (uint32_t)K * 256;
    constexpr uint32_t OFF_A_HI = (uint32_t)K * 512;
    constexpr uint32_t OFF_A_LO = (uint32_t)K * 512 + 32768;
    constexpr uint32_t OFF_RED  = (uint32_t)K * 512 + 65536;

    extern __shared__ __align__(128) char smem[];
    const uint32_t sb = smem_u32(smem);
    const int tid = threadIdx.x, lane = tid & 31, wid = tid >> 5;
    const int wr = wid & 3, wc = wid >> 2;

    // ---- W load + bf16 split into XOR-swizzled smem (once per block) ----
    for (int p = tid; p < K * 64; p += 256) {
        int k = p >> 6, np = p & 63, n = np * 2;
        float2 wv = *(const float2*)(W + (long)k * 128 + n);
        __nv_bfloat162 hp, lp;
        hp.x = __float2bfloat16(wv.x);
        hp.y = __float2bfloat16(wv.y);
        lp.x = __float2bfloat16(wv.x - __bfloat162float(hp.x));
        lp.y = __float2bfloat16(wv.y - __bfloat162float(hp.y));
        uint32_t off = (uint32_t)k * 256 +
                       ((((uint32_t)n >> 3) ^ ((uint32_t)k & 7)) << 4) + ((n & 7) << 1);
        *(__nv_bfloat162*)(smem + off) = hp;
        *(__nv_bfloat162*)(smem + OFF_B_LO + off) = lp;
    }
    __syncthreads();

    const float lwv = FUSE ? lw[0] : 0.f;
    const int ntiles = (M + 127) >> 7;
    float2 pref[32];

    auto prefetch = [&](int t, int kc) {
        #pragma unroll
        for (int i = 0; i < 32; i++) {
            int p = i * 256 + tid;
            int r = p >> 6, pc = p & 63;
            long row = (long)t * 128 + r;
            float2 v = make_float2(0.f, 0.f);
            if (row < M) v = *(const float2*)(A + row * (long)K + kc * 128 + pc * 2);
            pref[i] = v;
        }
    };

    int tile = blockIdx.x;
    if (tile < ntiles) prefetch(tile, 0);

    for (; tile < ntiles; tile += gridDim.x) {
        float acc[2][8][4];
        #pragma unroll
        for (int m = 0; m < 2; m++)
            #pragma unroll
            for (int nb = 0; nb < 8; nb++)
                #pragma unroll
                for (int c = 0; c < 4; c++) acc[m][nb][c] = 0.f;

        for (int kc = 0; kc < KCH; kc++) {
            __syncthreads();   // all warps done reading previous A chunk
            // convert + store A chunk hi/lo to swizzled smem
            #pragma unroll
            for (int i = 0; i < 32; i++) {
                int p = i * 256 + tid;
                int r = p >> 6, pc = p & 63, col = pc * 2;
                float2 v = pref[i];
                __nv_bfloat162 hp, lp;
                hp.x = __float2bfloat16(v.x);
                hp.y = __float2bfloat16(v.y);
                lp.x = __float2bfloat16(v.x - __bfloat162float(hp.x));
                lp.y = __float2bfloat16(v.y - __bfloat162float(hp.y));
                uint32_t off = (uint32_t)r * 256 +
                               ((((uint32_t)col >> 3) ^ ((uint32_t)r & 7)) << 4) +
                               ((col & 7) << 1);
                *(__nv_bfloat162*)(smem + OFF_A_HI + off) = hp;
                *(__nv_bfloat162*)(smem + OFF_A_LO + off) = lp;
            }
            __syncthreads();

            // issue next chunk's LDGs now — they overlap the HMMA below
            {
                int nkc = kc + 1, nt = tile;
                if (nkc == KCH) { nkc = 0; nt = tile + gridDim.x; }
                if (nt < ntiles) prefetch(nt, nkc);
            }

            // 8 k16 steps over this 128-wide chunk
            #pragma unroll
            for (int s = 0; s < 8; s++) {
                uint32_t a_hi[2][4], a_lo[2][4];
                #pragma unroll
                for (int m = 0; m < 2; m++) {
                    uint32_t r = (uint32_t)(wr * 32 + m * 16 + (lane & 15));
                    uint32_t ch = (uint32_t)(s * 2 + (lane >> 4));
                    uint32_t off = r * 256 + (((ch ^ (r & 7)) << 4));
                    ldsm_x4(a_hi[m], sb + OFF_A_HI + off);
                    ldsm_x4(a_lo[m], sb + OFF_A_LO + off);
                }
                uint32_t b_hi[4][4], b_lo[4][4];
                #pragma unroll
                for (int p4 = 0; p4 < 4; p4++) {
                    uint32_t k = (uint32_t)(kc * 128 + s * 16 + (lane & 15));
                    uint32_t nch = (uint32_t)(wc * 8 + p4 * 2 + (lane >> 4));
                    uint32_t off = k * 256 + (((nch ^ (k & 7)) << 4));
                    ldsm_x4t(b_hi[p4], sb + off);
                    ldsm_x4t(b_lo[p4], sb + OFF_B_LO + off);
                }
                #pragma unroll
                for (int m = 0; m < 2; m++)
                    #pragma unroll
                    for (int p4 = 0; p4 < 4; p4++)
                        #pragma unroll
                        for (int h = 0; h < 2; h++) {
                            float* d = acc[m][p4 * 2 + h];
                            mma_bf16(d, a_hi[m], &b_hi[p4][2 * h]);
                            mma_bf16(d, a_hi[m], &b_lo[p4][2 * h]);
                            mma_bf16(d, a_lo[m], &b_hi[p4][2 * h]);
                        }
            }
        }

        // ---- epilogue: C store (+ fused DistMult) ----
        float* red = (float*)(smem + OFF_RED);
        #pragma unroll
        for (int m = 0; m < 2; m++) {
            #pragma unroll
            for (int cp = 0; cp < 4; cp += 2) {
                int r = wr * 32 + m * 16 + (lane >> 2) + (cp ? 8 : 0);
                long grow = (long)tile * 128 + r;
                if (grow < M) {
                    float* crow = C + grow * 128 + wc * 64 + (lane & 3) * 2;
                    float part = 0.f;
                    const float *hq = nullptr, *tq = nullptr;
                    if (FUSE) {
                        long src = ld_idx(eidx, grow);
                        long dst = ld_idx(eidx, (long)E_EDGES + grow);
                        hq = axw + src * 128 + wc * 64 + (lane & 3) * 2;
                        tq = axw + dst * 128 + wc * 64 + (lane & 3) * 2;
                    }
                    #pragma unroll
                    for (int nb = 0; nb < 8; nb++) {
                        float2 v = make_float2(acc[m][nb][cp], acc[m][nb][cp + 1]);
                        *(float2*)(crow + nb * 8) = v;
                        if (FUSE) {
                            float2 h2 = *(const float2*)(hq + nb * 8);
                            float2 t2 = *(const float2*)(tq + nb * 8);
                            part = fmaf(v.x * h2.x, t2.x, part);
                            part = fmaf(v.y * h2.y, t2.y, part);
                        }
                    }
                    if (FUSE) {
                        part += __shfl_xor_sync(0xFFFFFFFFu, part, 1);
                        part += __shfl_xor_sync(0xFFFFFFFFu, part, 2);
                        if ((lane & 3) == 0) red[wc * 128 + r] = part;
                    }
                }
            }
        }
        if (FUSE) {
            __syncthreads();
            if (tid < 128) {
                long g2 = (long)tile * 128 + tid;
                float sc = red[tid] + red[128 + tid];
                scores[g2] = sc * tcl[g2] * lwv;
            }
        }
    }
}

// ---------------------------------------------------------------------------
// Scatter-add: axw[dst] += xw[src]  via no-return vector reduction
// ---------------------------------------------------------------------------
__global__ void scatter_kernel(const void* __restrict__ eidx,
                               const float* __restrict__ xw,
                               float* __restrict__ axw) {
    long t = (long)blockIdx.x * blockDim.x + threadIdx.x;
    if (t >= (long)E_EDGES * 32) return;
    long e = t >> 5;
    int  q = (int)(t & 31) * 4;
    long src = ld_idx(eidx, e);
    long dst = ld_idx(eidx, (long)E_EDGES + e);
    float4 v = *(const float4*)&xw[src * 128 + q];
    float* o = &axw[dst * 128 + q];
    asm volatile("red.global.add.v4.f32 [%0], {%1, %2, %3, %4};"
                 :: "l"(o), "f"(v.x), "f"(v.y), "f"(v.z), "f"(v.w) : "memory");
}

// ---------------------------------------------------------------------------
// Launch
// ---------------------------------------------------------------------------
extern "C" void kernel_launch(void* const* d_in, const int* in_sizes, int n_in,
                              void* d_out, int out_size) {
    const float* x    = (const float*)d_in[0];   // [N, 256]
    const float* ea   = (const float*)d_in[1];   // [E, 128]
    const float* tc   = (const float*)d_in[2];   // [E]
    const float* wn   = (const float*)d_in[3];   // [256, 128]
    const float* we   = (const float*)d_in[4];   // [128, 128]
    const float* lw   = (const float*)d_in[5];   // [1]
    const void*  eidx = d_in[6];                 // [2, E] int32 or int64

    float* out    = (float*)d_out;
    float* axw    = out;                               // [N, 128]
    float* ew     = out + (long)N_NODES * 128;         // [E, 128]
    float* scores = ew + (long)E_EDGES * 128;          // [E]

    float* xw;
    cudaGetSymbolAddress((void**)&xw, g_xw);

    const int SMEM_XW = 256 * 512 + 65536 + 1024;   // 197632
    const int SMEM_EW = 128 * 512 + 65536 + 1024;   // 132096
    cudaFuncSetAttribute(gemm_mma_kernel<2, false>,
                         cudaFuncAttributeMaxDynamicSharedMemorySize, SMEM_XW);
    cudaFuncSetAttribute(gemm_mma_kernel<1, true>,
                         cudaFuncAttributeMaxDynamicSharedMemorySize, SMEM_EW);

    // 1) dtype detection
    detect_idx_kernel<<<1, 32>>>(eidx);

    // 2) zero axw (accumulated via reductions)
    {
        int n4 = N_NODES * 128 / 4;
        zero4_kernel<<<(n4 + 255) / 256, 256>>>((float4*)axw, n4);
    }

    // 3) xw = x @ Wn  (bf16x3 HMMA, K=256)
    gemm_mma_kernel<2, false><<<152, 256, SMEM_XW>>>(
        x, wn, xw, N_NODES, nullptr, nullptr, nullptr, nullptr, nullptr);

    // 4) axw = segment_sum(xw[src], dst)
    {
        long total = (long)E_EDGES * 32;
        scatter_kernel<<<(int)((total + 255) / 256), 256>>>(eidx, xw, axw);
    }

    // 5) ew = edge_attr @ We + fused DistMult scores (bf16x3 HMMA, K=128)
    gemm_mma_kernel<1, true><<<152, 256, SMEM_EW>>>(
        ea, we, ew, E_EDGES, eidx, axw, tc, lw, scores);
}

// round 4
// speedup vs baseline: 2.1806x; 1.1169x over previous
#include <cuda_runtime.h>
#include <cuda_bf16.h>
#include <cstdint>

#define N_NODES 100000
#define E_EDGES 640000

// ---------------------------------------------------------------------------
// Global scratch
// ---------------------------------------------------------------------------
__device__ float g_xw[(size_t)N_NODES * 128];   // x @ Wn
__device__ int   g_idx64;                        // edge_index dtype flag

// ---------------------------------------------------------------------------
// Helpers
// ---------------------------------------------------------------------------
__device__ __forceinline__ uint32_t smem_u32(const void* p) {
    uint32_t a;
    asm("{ .reg .u64 t; cvta.to.shared.u64 t, %1; cvt.u32.u64 %0, t; }"
        : "=r"(a) : "l"(p));
    return a;
}

__device__ __forceinline__ void mma_bf16(float* d, const uint32_t* a, const uint32_t* b) {
    asm volatile(
        "mma.sync.aligned.m16n8k16.row.col.f32.bf16.bf16.f32 "
        "{%0,%1,%2,%3}, {%4,%5,%6,%7}, {%8,%9}, {%0,%1,%2,%3};"
        : "+f"(d[0]), "+f"(d[1]), "+f"(d[2]), "+f"(d[3])
        : "r"(a[0]), "r"(a[1]), "r"(a[2]), "r"(a[3]), "r"(b[0]), "r"(b[1]));
}

__device__ __forceinline__ void ldsm_x4(uint32_t* r, uint32_t addr) {
    asm volatile("ldmatrix.sync.aligned.m8n8.x4.shared.b16 {%0,%1,%2,%3}, [%4];"
                 : "=r"(r[0]), "=r"(r[1]), "=r"(r[2]), "=r"(r[3]) : "r"(addr));
}
__device__ __forceinline__ void ldsm_x4t(uint32_t* r, uint32_t addr) {
    asm volatile("ldmatrix.sync.aligned.m8n8.x4.trans.shared.b16 {%0,%1,%2,%3}, [%4];"
                 : "=r"(r[0]), "=r"(r[1]), "=r"(r[2]), "=r"(r[3]) : "r"(addr));
}

__device__ __forceinline__ void split2(float2 v, __nv_bfloat162& hp, __nv_bfloat162& lp) {
    hp.x = __float2bfloat16(v.x);
    hp.y = __float2bfloat16(v.y);
    lp.x = __float2bfloat16(v.x - __bfloat162float(hp.x));
    lp.y = __float2bfloat16(v.y - __bfloat162float(hp.y));
}

// ---------------------------------------------------------------------------
// edge_index dtype detection (int32 vs int64)
// ---------------------------------------------------------------------------
__global__ void detect_idx_kernel(const void* __restrict__ eidx) {
    if (threadIdx.x == 0 && blockIdx.x == 0) {
        const unsigned long long* p = (const unsigned long long*)eidx;
        int ok = 1;
        #pragma unroll 1
        for (int i = 0; i < 64; i++)
            if (p[i] >= (unsigned long long)N_NODES) { ok = 0; break; }
        g_idx64 = ok;
    }
}

__device__ __forceinline__ long ld_idx(const void* __restrict__ p, long i) {
    if (g_idx64) return (long)((const long long*)p)[i];
    return (long)((const int*)p)[i];
}

__global__ void zero4_kernel(float4* __restrict__ p, int n4) {
    int i = blockIdx.x * blockDim.x + threadIdx.x;
    if (i < n4) p[i] = make_float4(0.f, 0.f, 0.f, 0.f);
}

// ---------------------------------------------------------------------------
// xw kernel: C[M x 128] = A[M x 256] @ W[256 x 128], bf16x3 HMMA (as R3,
// plus streaming loads for A). Single-buffer; xw is the minor cost.
// ---------------------------------------------------------------------------
__global__ __launch_bounds__(256, 1)
void gemm_xw_kernel(const float* __restrict__ A, const float* __restrict__ W,
                    float* __restrict__ C, int M) {
    constexpr int K = 256;
    constexpr uint32_t OFF_B_LO = (uint32_t)K * 256;     // 65536
    constexpr uint32_t OFF_A_HI = (uint32_t)K * 512;     // 131072
    constexpr uint32_t OFF_A_LO = OFF_A_HI + 32768;

    extern __shared__ __align__(128) char smem[];
    const uint32_t sb = smem_u32(smem);
    const int tid = threadIdx.x, lane = tid & 31, wid = tid >> 5;
    const int wr = wid & 3, wc = wid >> 2;

    for (int p = tid; p < K * 64; p += 256) {
        int k = p >> 6, n = (p & 63) * 2;
        float2 wv = *(const float2*)(W + (long)k * 128 + n);
        __nv_bfloat162 hp, lp; split2(wv, hp, lp);
        uint32_t off = (uint32_t)k * 256 +
                       ((((uint32_t)n >> 3) ^ ((uint32_t)k & 7)) << 4) + ((n & 7) << 1);
        *(__nv_bfloat162*)(smem + off) = hp;
        *(__nv_bfloat162*)(smem + OFF_B_LO + off) = lp;
    }
    __syncthreads();

    const int ntiles = (M + 127) >> 7;
    float2 pref[32];

    auto prefetch = [&](int t, int kc) {
        #pragma unroll
        for (int i = 0; i < 32; i++) {
            int p = i * 256 + tid;
            int r = p >> 6, pc = p & 63;
            long row = (long)t * 128 + r;
            float2 v = make_float2(0.f, 0.f);
            if (row < M) v = __ldcs((const float2*)(A + row * (long)K + kc * 128 + pc * 2));
            pref[i] = v;
        }
    };

    int tile = blockIdx.x;
    if (tile < ntiles) prefetch(tile, 0);

    for (; tile < ntiles; tile += gridDim.x) {
        float acc[2][8][4];
        #pragma unroll
        for (int m = 0; m < 2; m++)
            #pragma unroll
            for (int nb = 0; nb < 8; nb++)
                #pragma unroll
                for (int c = 0; c < 4; c++) acc[m][nb][c] = 0.f;

        for (int kc = 0; kc < 2; kc++) {
            __syncthreads();
            #pragma unroll
            for (int i = 0; i < 32; i++) {
                int p = i * 256 + tid;
                int r = p >> 6, col = (p & 63) * 2;
                __nv_bfloat162 hp, lp; split2(pref[i], hp, lp);
                uint32_t off = (uint32_t)r * 256 +
                               ((((uint32_t)col >> 3) ^ ((uint32_t)r & 7)) << 4) +
                               ((col & 7) << 1);
                *(__nv_bfloat162*)(smem + OFF_A_HI + off) = hp;
                *(__nv_bfloat162*)(smem + OFF_A_LO + off) = lp;
            }
            __syncthreads();
            {
                int nkc = kc + 1, nt = tile;
                if (nkc == 2) { nkc = 0; nt = tile + gridDim.x; }
                if (nt < ntiles) prefetch(nt, nkc);
            }
            #pragma unroll
            for (int s = 0; s < 8; s++) {
                uint32_t a_hi[2][4], a_lo[2][4];
                #pragma unroll
                for (int m = 0; m < 2; m++) {
                    uint32_t r = (uint32_t)(wr * 32 + m * 16 + (lane & 15));
                    uint32_t ch = (uint32_t)(s * 2 + (lane >> 4));
                    uint32_t off = r * 256 + (((ch ^ (r & 7)) << 4));
                    ldsm_x4(a_hi[m], sb + OFF_A_HI + off);
                    ldsm_x4(a_lo[m], sb + OFF_A_LO + off);
                }
                uint32_t b_hi[4][4], b_lo[4][4];
                #pragma unroll
                for (int p4 = 0; p4 < 4; p4++) {
                    uint32_t k = (uint32_t)(kc * 128 + s * 16 + (lane & 15));
                    uint32_t nch = (uint32_t)(wc * 8 + p4 * 2 + (lane >> 4));
                    uint32_t off = k * 256 + (((nch ^ (k & 7)) << 4));
                    ldsm_x4t(b_hi[p4], sb + off);
                    ldsm_x4t(b_lo[p4], sb + OFF_B_LO + off);
                }
                #pragma unroll
                for (int m = 0; m < 2; m++)
                    #pragma unroll
                    for (int p4 = 0; p4 < 4; p4++)
                        #pragma unroll
                        for (int h = 0; h < 2; h++) {
                            float* d = acc[m][p4 * 2 + h];
                            mma_bf16(d, a_hi[m], &b_hi[p4][2 * h]);
                            mma_bf16(d, a_hi[m], &b_lo[p4][2 * h]);
                            mma_bf16(d, a_lo[m], &b_hi[p4][2 * h]);
                        }
            }
        }
        #pragma unroll
        for (int m = 0; m < 2; m++)
            #pragma unroll
            for (int cp = 0; cp < 4; cp += 2) {
                int r = wr * 32 + m * 16 + (lane >> 2) + (cp ? 8 : 0);
                long grow = (long)tile * 128 + r;
                if (grow < M) {
                    float* crow = C + grow * 128 + wc * 64 + (lane & 3) * 2;
                    #pragma unroll
                    for (int nb = 0; nb < 8; nb++)
                        *(float2*)(crow + nb * 8) =
                            make_float2(acc[m][nb][cp], acc[m][nb][cp + 1]);
                }
            }
    }
}

// ---------------------------------------------------------------------------
// ew kernel: C[E x 128] = A[E x 128] @ W[128 x 128] + fused DistMult scores.
// Cross-tile A double-buffering, 1 sync/tile, index preload, streaming hints.
// Smem: W hi/lo 64KB @0, A bufs 2x64KB @65536, red 2x1KB @196608.
// ---------------------------------------------------------------------------
__global__ __launch_bounds__(256, 1)
void gemm_ew_kernel(const float* __restrict__ A, const float* __restrict__ W,
                    float* __restrict__ C,
                    const void* __restrict__ eidx,
                    const float* __restrict__ axw,
                    const float* __restrict__ tcl,
                    const float* __restrict__ lw,
                    float* __restrict__ scores) {
    constexpr int M = E_EDGES;
    constexpr uint32_t OFF_B_LO = 32768;
    constexpr uint32_t OFF_A    = 65536;     // + buf*65536 (+32768 for lo)
    constexpr uint32_t OFF_RED  = 196608;    // + cur*1024

    extern __shared__ __align__(128) char smem[];
    const uint32_t sb = smem_u32(smem);
    const int tid = threadIdx.x, lane = tid & 31, wid = tid >> 5;
    const int wr = wid & 3, wc = wid >> 2;

    // W load + split (once)
    for (int p = tid; p < 128 * 64; p += 256) {
        int k = p >> 6, n = (p & 63) * 2;
        float2 wv = *(const float2*)(W + (long)k * 128 + n);
        __nv_bfloat162 hp, lp; split2(wv, hp, lp);
        uint32_t off = (uint32_t)k * 256 +
                       ((((uint32_t)n >> 3) ^ ((uint32_t)k & 7)) << 4) + ((n & 7) << 1);
        *(__nv_bfloat162*)(smem + off) = hp;
        *(__nv_bfloat162*)(smem + OFF_B_LO + off) = lp;
    }

    const float lwv = lw[0];
    const int ntiles = M >> 7;              // E divisible by 128
    float2 pref[32];

    auto prefetch = [&](int t) {
        #pragma unroll
        for (int i = 0; i < 32; i++) {
            int p = i * 256 + tid;
            int r = p >> 6, pc = p & 63;
            pref[i] = __ldcs((const float2*)(A + ((long)t * 128 + r) * 128 + pc * 2));
        }
    };
    auto store_buf = [&](int b) {
        #pragma unroll
        for (int i = 0; i < 32; i++) {
            int p = i * 256 + tid;
            int r = p >> 6, col = (p & 63) * 2;
            __nv_bfloat162 hp, lp; split2(pref[i], hp, lp);
            uint32_t off = (uint32_t)r * 256 +
                           ((((uint32_t)col >> 3) ^ ((uint32_t)r & 7)) << 4) +
                           ((col & 7) << 1);
            *(__nv_bfloat162*)(smem + OFF_A + (uint32_t)b * 65536 + off) = hp;
            *(__nv_bfloat162*)(smem + OFF_A + (uint32_t)b * 65536 + 32768 + off) = lp;
        }
    };

    int tile = blockIdx.x;
    const int G = gridDim.x;
    if (tile < ntiles) {
        prefetch(tile);
        store_buf(0);
        if (tile + G < ntiles) prefetch(tile + G);
    }
    __syncthreads();

    int cur = 0;
    for (; tile < ntiles; tile += G) {
        // stage tile+1 into the other buffer (regs already hold it); then
        // kick off LDGs for tile+2 so they complete during this tile's MMA.
        if (tile + G < ntiles) store_buf(cur ^ 1);
        if (tile + 2 * G < ntiles) prefetch(tile + 2 * G);

        // preload edge indices for this tile's epilogue rows
        const int r0 = wr * 32 + (lane >> 2);
        int isrc[4], idst[4];
        #pragma unroll
        for (int j = 0; j < 4; j++) {
            long grow = (long)tile * 128 + r0 + j * 8;
            isrc[j] = (int)ld_idx(eidx, grow);
            idst[j] = (int)ld_idx(eidx, (long)E_EDGES + grow);
        }

        float acc[2][8][4];
        #pragma unroll
        for (int m = 0; m < 2; m++)
            #pragma unroll
            for (int nb = 0; nb < 8; nb++)
                #pragma unroll
                for (int c = 0; c < 4; c++) acc[m][nb][c] = 0.f;

        const uint32_t abase = sb + OFF_A + (uint32_t)cur * 65536;
        #pragma unroll
        for (int s = 0; s < 8; s++) {
            uint32_t a_hi[2][4], a_lo[2][4];
            #pragma unroll
            for (int m = 0; m < 2; m++) {
                uint32_t r = (uint32_t)(wr * 32 + m * 16 + (lane & 15));
                uint32_t ch = (uint32_t)(s * 2 + (lane >> 4));
                uint32_t off = r * 256 + (((ch ^ (r & 7)) << 4));
                ldsm_x4(a_hi[m], abase + off);
                ldsm_x4(a_lo[m], abase + 32768 + off);
            }
            uint32_t b_hi[4][4], b_lo[4][4];
            #pragma unroll
            for (int p4 = 0; p4 < 4; p4++) {
                uint32_t k = (uint32_t)(s * 16 + (lane & 15));
                uint32_t nch = (uint32_t)(wc * 8 + p4 * 2 + (lane >> 4));
                uint32_t off = k * 256 + (((nch ^ (k & 7)) << 4));
                ldsm_x4t(b_hi[p4], sb + off);
                ldsm_x4t(b_lo[p4], sb + OFF_B_LO + off);
            }
            #pragma unroll
            for (int m = 0; m < 2; m++)
                #pragma unroll
                for (int p4 = 0; p4 < 4; p4++)
                    #pragma unroll
                    for (int h = 0; h < 2; h++) {
                        float* d = acc[m][p4 * 2 + h];
                        mma_bf16(d, a_hi[m], &b_hi[p4][2 * h]);
                        mma_bf16(d, a_hi[m], &b_lo[p4][2 * h]);
                        mma_bf16(d, a_lo[m], &b_hi[p4][2 * h]);
                    }
        }

        // epilogue: streamed C store + DistMult partials
        float* red = (float*)(smem + OFF_RED + (uint32_t)cur * 1024);
        #pragma unroll
        for (int j = 0; j < 4; j++) {
            const int m = j >> 1, cp = (j & 1) * 2;
            const int r = r0 + j * 8;
            long grow = (long)tile * 128 + r;
            float* crow = C + grow * 128 + wc * 64 + (lane & 3) * 2;
            const float* hq = axw + (long)isrc[j] * 128 + wc * 64 + (lane & 3) * 2;
            const float* tq = axw + (long)idst[j] * 128 + wc * 64 + (lane & 3) * 2;
            float part = 0.f;
            #pragma unroll
            for (int nb = 0; nb < 8; nb++) {
                float2 v = make_float2(acc[m][nb][cp], acc[m][nb][cp + 1]);
                __stcs((float2*)(crow + nb * 8), v);
                float2 h2 = *(const float2*)(hq + nb * 8);
                float2 t2 = *(const float2*)(tq + nb * 8);
                part = fmaf(v.x * h2.x, t2.x, part);
                part = fmaf(v.y * h2.y, t2.y, part);
            }
            part += __shfl_xor_sync(0xFFFFFFFFu, part, 1);
            part += __shfl_xor_sync(0xFFFFFFFFu, part, 2);
            if ((lane & 3) == 0) red[wc * 128 + r] = part;
        }
        __syncthreads();    // publishes buf[cur^1] for next tile + red for scores
        if (tid < 128) {
            long g2 = (long)tile * 128 + tid;
            scores[g2] = (red[tid] + red[128 + tid]) * tcl[g2] * lwv;
        }
        cur ^= 1;
    }
}

// ---------------------------------------------------------------------------
// Scatter-add: axw[dst] += xw[src].  Warp per edge; lane 0/1 load the two
// indices once, broadcast via shfl (kills 31/32 of the index traffic).
// ---------------------------------------------------------------------------
__global__ void scatter_kernel(const void* __restrict__ eidx,
                               const float* __restrict__ xw,
                               float* __restrict__ axw) {
    long t = (long)blockIdx.x * blockDim.x + threadIdx.x;
    long e = t >> 5;
    if (e >= E_EDGES) return;
    int lane = threadIdx.x & 31;
    long vi = 0;
    if (lane < 2) vi = ld_idx(eidx, lane ? (long)E_EDGES + e : e);
    long src = __shfl_sync(0xFFFFFFFFu, vi, 0);
    long dst = __shfl_sync(0xFFFFFFFFu, vi, 1);
    int q = (int)(t & 31) * 4;
    float4 v = *(const float4*)&xw[src * 128 + q];
    float* o = &axw[dst * 128 + q];
    asm volatile("red.global.add.v4.f32 [%0], {%1, %2, %3, %4};"
                 :: "l"(o), "f"(v.x), "f"(v.y), "f"(v.z), "f"(v.w) : "memory");
}

// ---------------------------------------------------------------------------
// Launch
// ---------------------------------------------------------------------------
extern "C" void kernel_launch(void* const* d_in, const int* in_sizes, int n_in,
                              void* d_out, int out_size) {
    const float* x    = (const float*)d_in[0];   // [N, 256]
    const float* ea   = (const float*)d_in[1];   // [E, 128]
    const float* tc   = (const float*)d_in[2];   // [E]
    const float* wn   = (const float*)d_in[3];   // [256, 128]
    const float* we   = (const float*)d_in[4];   // [128, 128]
    const float* lw   = (const float*)d_in[5];   // [1]
    const void*  eidx = d_in[6];                 // [2, E] int32 or int64

    float* out    = (float*)d_out;
    float* axw    = out;                               // [N, 128]
    float* ew     = out + (long)N_NODES * 128;         // [E, 128]
    float* scores = ew + (long)E_EDGES * 128;          // [E]

    float* xw;
    cudaGetSymbolAddress((void**)&xw, g_xw);

    const int SMEM_XW = 256 * 512 + 65536;            // 196608
    const int SMEM_EW = 65536 + 2 * 65536 + 2048;     // 198656
    cudaFuncSetAttribute(gemm_xw_kernel,
                         cudaFuncAttributeMaxDynamicSharedMemorySize, SMEM_XW);
    cudaFuncSetAttribute(gemm_ew_kernel,
                         cudaFuncAttributeMaxDynamicSharedMemorySize, SMEM_EW);

    // 1) dtype detection
    detect_idx_kernel<<<1, 32>>>(eidx);

    // 2) zero axw (accumulated via reductions)
    {
        int n4 = N_NODES * 128 / 4;
        zero4_kernel<<<(n4 + 255) / 256, 256>>>((float4*)axw, n4);
    }

    // 3) xw = x @ Wn
    gemm_xw_kernel<<<152, 256, SMEM_XW>>>(x, wn, xw, N_NODES);

    // 4) axw = segment_sum(xw[src], dst)
    {
        long total = (long)E_EDGES * 32;
        scatter_kernel<<<(int)((total + 255) / 256), 256>>>(eidx, xw, axw);
    }

    // 5) ew = edge_attr @ We + fused DistMult scores
    gemm_ew_kernel<<<152, 256, SMEM_EW>>>(ea, we, ew, eidx, axw, tc, lw, scores);
}

// round 5
// speedup vs baseline: 2.5523x; 1.1705x over previous
#include <cuda_runtime.h>
#include <cuda_fp16.h>
#include <cstdint>

#define N_NODES 100000
#define E_EDGES 640000

// ---------------------------------------------------------------------------
// Global scratch
// ---------------------------------------------------------------------------
__device__ float g_xw[(size_t)N_NODES * 128];   // x @ Wn
__device__ int   g_idx64;                        // edge_index dtype flag

// ---------------------------------------------------------------------------
// Helpers
// ---------------------------------------------------------------------------
__device__ __forceinline__ uint32_t smem_u32(const void* p) {
    uint32_t a;
    asm("{ .reg .u64 t; cvta.to.shared.u64 t, %1; cvt.u32.u64 %0, t; }"
        : "=r"(a) : "l"(p));
    return a;
}

__device__ __forceinline__ void mma_f16(float* d, const uint32_t* a, const uint32_t* b) {
    asm volatile(
        "mma.sync.aligned.m16n8k16.row.col.f32.f16.f16.f32 "
        "{%0,%1,%2,%3}, {%4,%5,%6,%7}, {%8,%9}, {%0,%1,%2,%3};"
        : "+f"(d[0]), "+f"(d[1]), "+f"(d[2]), "+f"(d[3])
        : "r"(a[0]), "r"(a[1]), "r"(a[2]), "r"(a[3]), "r"(b[0]), "r"(b[1]));
}

__device__ __forceinline__ void ldsm_x4(uint32_t* r, uint32_t addr) {
    asm volatile("ldmatrix.sync.aligned.m8n8.x4.shared.b16 {%0,%1,%2,%3}, [%4];"
                 : "=r"(r[0]), "=r"(r[1]), "=r"(r[2]), "=r"(r[3]) : "r"(addr));
}
__device__ __forceinline__ void ldsm_x4t(uint32_t* r, uint32_t addr) {
    asm volatile("ldmatrix.sync.aligned.m8n8.x4.trans.shared.b16 {%0,%1,%2,%3}, [%4];"
                 : "=r"(r[0]), "=r"(r[1]), "=r"(r[2]), "=r"(r[3]) : "r"(addr));
}

// ---------------------------------------------------------------------------
// edge_index dtype detection (int32 vs int64)
// ---------------------------------------------------------------------------
__global__ void detect_idx_kernel(const void* __restrict__ eidx) {
    if (threadIdx.x == 0 && blockIdx.x == 0) {
        const unsigned long long* p = (const unsigned long long*)eidx;
        int ok = 1;
        #pragma unroll 1
        for (int i = 0; i < 64; i++)
            if (p[i] >= (unsigned long long)N_NODES) { ok = 0; break; }
        g_idx64 = ok;
    }
}

__device__ __forceinline__ long ld_idx(const void* __restrict__ p, long i) {
    if (g_idx64) return (long)((const long long*)p)[i];
    return (long)((const int*)p)[i];
}

__global__ void zero4_kernel(float4* __restrict__ p, int n4) {
    int i = blockIdx.x * blockDim.x + threadIdx.x;
    if (i < n4) p[i] = make_float4(0.f, 0.f, 0.f, 0.f);
}

// ---------------------------------------------------------------------------
// Unified persistent GEMM: C[M x 128] = A[M x K] @ W[K x 128], K = KCH*128.
// Precision: A -> fp16 (single), W -> fp16 hi + lo; 2 MMA passes:
//   C = Ah*Wh + Ah*Wl   (error ~ eA*W ~ 3e-4 rel, well under 1e-3)
// Cross-chunk A double-buffering, 1 __syncthreads per 128-k chunk.
// FUSE: DistMult scores from accumulator fragments in the epilogue.
//
// Smem layout:
//   [0, K*256)          W hi  (fp16, swizzled, k-row stride 256B)
//   [K*256, K*512)      W lo
//   [K*512, +65536)     A chunk bufs: 2 x 32768 (128x128 fp16)
//   [K*512+65536, +2KB) score reduction bufs (2 x 1KB)
// ---------------------------------------------------------------------------
template<int KCH, bool FUSE>
__global__ __launch_bounds__(256, 1)
void gemm_kernel(const float* __restrict__ A, const float* __restrict__ W,
                 float* __restrict__ C, int M,
                 const void* __restrict__ eidx,
                 const float* __restrict__ axw,
                 const float* __restrict__ tcl,
                 const float* __restrict__ lw,
                 float* __restrict__ scores) {
    constexpr int K = KCH * 128;
    constexpr uint32_t OFF_WLO = (uint32_t)K * 256;
    constexpr uint32_t OFF_A   = (uint32_t)K * 512;
    constexpr uint32_t OFF_RED = OFF_A + 65536;

    extern __shared__ __align__(128) char smem[];
    const uint32_t sb = smem_u32(smem);
    const int tid = threadIdx.x, lane = tid & 31, wid = tid >> 5;
    const int wr = wid & 3, wc = wid >> 2;

    // ---- W load + fp16 hi/lo split into swizzled smem (once) ----
    for (int p = tid; p < K * 64; p += 256) {
        int k = p >> 6, n = (p & 63) * 2;
        float2 wv = *(const float2*)(W + (long)k * 128 + n);
        __half2 hp = __floats2half2_rn(wv.x, wv.y);
        __half2 lp = __floats2half2_rn(wv.x - __low2float(hp),
                                       wv.y - __high2float(hp));
        uint32_t off = (uint32_t)k * 256 +
                       ((((uint32_t)n >> 3) ^ ((uint32_t)k & 7)) << 4) + ((n & 7) << 1);
        *(__half2*)(smem + off) = hp;
        *(__half2*)(smem + OFF_WLO + off) = lp;
    }

    const float lwv = FUSE ? lw[0] : 0.f;
    const int ntiles = (M + 127) >> 7;
    const int G = gridDim.x;
    float2 pref[32];

    auto prefetch = [&](int t, int kc) {
        #pragma unroll
        for (int i = 0; i < 32; i++) {
            int p = i * 256 + tid;
            int r = p >> 6, pc = p & 63;
            long row = (long)t * 128 + r;
            float2 v = make_float2(0.f, 0.f);
            if (row < M) v = __ldcs((const float2*)(A + row * (long)K + kc * 128 + pc * 2));
            pref[i] = v;
        }
    };
    auto store_buf = [&](int b) {
        #pragma unroll
        for (int i = 0; i < 32; i++) {
            int p = i * 256 + tid;
            int r = p >> 6, col = (p & 63) * 2;
            __half2 hp = __floats2half2_rn(pref[i].x, pref[i].y);
            uint32_t off = (uint32_t)r * 256 +
                           ((((uint32_t)col >> 3) ^ ((uint32_t)r & 7)) << 4) +
                           ((col & 7) << 1);
            *(__half2*)(smem + OFF_A + (uint32_t)b * 32768 + off) = hp;
        }
    };

    int tile = blockIdx.x;
    if (tile < ntiles) {
        prefetch(tile, 0);
        store_buf(0);
        int nt = tile, nkc = 1;
        if (KCH == 1) { nt = tile + G; nkc = 0; }
        if (nt < ntiles) prefetch(nt, nkc);
    }
    __syncthreads();

    int cur = 0, rcur = 0;
    for (; tile < ntiles; tile += G) {
        float acc[2][8][4];
        #pragma unroll
        for (int m = 0; m < 2; m++)
            #pragma unroll
            for (int nb = 0; nb < 8; nb++)
                #pragma unroll
                for (int c = 0; c < 4; c++) acc[m][nb][c] = 0.f;

        const int r0 = wr * 32 + (lane >> 2);
        int isrc[4], idst[4];
        if (FUSE) {
            #pragma unroll
            for (int j = 0; j < 4; j++) {
                long grow = (long)tile * 128 + r0 + j * 8;
                isrc[j] = (int)ld_idx(eidx, grow);
                idst[j] = (int)ld_idx(eidx, (long)E_EDGES + grow);
            }
        }

        for (int kc = 0; kc < KCH; kc++) {
            // regs hold the successor chunk of (tile, kc): stage it
            int nt1 = tile, nkc1 = kc + 1;
            if (nkc1 == KCH) { nkc1 = 0; nt1 = tile + G; }
            if (nt1 < ntiles) store_buf(cur ^ 1);
            int nt2 = nt1, nkc2 = nkc1 + 1;
            if (nkc2 == KCH) { nkc2 = 0; nt2 = nt1 + G; }
            if (nt2 < ntiles) prefetch(nt2, nkc2);

            const uint32_t abase = sb + OFF_A + (uint32_t)cur * 32768;
            #pragma unroll
            for (int s = 0; s < 8; s++) {
                uint32_t a[2][4];
                #pragma unroll
                for (int m = 0; m < 2; m++) {
                    uint32_t r = (uint32_t)(wr * 32 + m * 16 + (lane & 15));
                    uint32_t ch = (uint32_t)(s * 2 + (lane >> 4));
                    ldsm_x4(a[m], abase + r * 256 + (((ch ^ (r & 7)) << 4)));
                }
                uint32_t bh[4][4], bl[4][4];
                #pragma unroll
                for (int p4 = 0; p4 < 4; p4++) {
                    uint32_t k = (uint32_t)(kc * 128 + s * 16 + (lane & 15));
                    uint32_t nch = (uint32_t)(wc * 8 + p4 * 2 + (lane >> 4));
                    uint32_t off = k * 256 + (((nch ^ (k & 7)) << 4));
                    ldsm_x4t(bh[p4], sb + off);
                    ldsm_x4t(bl[p4], sb + OFF_WLO + off);
                }
                #pragma unroll
                for (int m = 0; m < 2; m++)
                    #pragma unroll
                    for (int p4 = 0; p4 < 4; p4++)
                        #pragma unroll
                        for (int h = 0; h < 2; h++) {
                            float* d = acc[m][p4 * 2 + h];
                            mma_f16(d, a[m], &bh[p4][2 * h]);
                            mma_f16(d, a[m], &bl[p4][2 * h]);
                        }
            }
            if (kc < KCH - 1) { __syncthreads(); cur ^= 1; }
        }

        // ---- epilogue: C store (+ fused DistMult partials) ----
        float* red = (float*)(smem + OFF_RED + (uint32_t)rcur * 1024);
        #pragma unroll
        for (int j = 0; j < 4; j++) {
            const int m = j >> 1, cp = (j & 1) * 2;
            const int r = r0 + j * 8;
            long grow = (long)tile * 128 + r;
            if (grow < M) {
                float* crow = C + grow * 128 + wc * 64 + (lane & 3) * 2;
                if (FUSE) {
                    const float* hq = axw + (long)isrc[j] * 128 + wc * 64 + (lane & 3) * 2;
                    const float* tq = axw + (long)idst[j] * 128 + wc * 64 + (lane & 3) * 2;
                    float part = 0.f;
                    #pragma unroll
                    for (int nb = 0; nb < 8; nb++) {
                        float2 v = make_float2(acc[m][nb][cp], acc[m][nb][cp + 1]);
                        __stcs((float2*)(crow + nb * 8), v);
                        float2 h2 = *(const float2*)(hq + nb * 8);
                        float2 t2 = *(const float2*)(tq + nb * 8);
                        part = fmaf(v.x * h2.x, t2.x, part);
                        part = fmaf(v.y * h2.y, t2.y, part);
                    }
                    part += __shfl_xor_sync(0xFFFFFFFFu, part, 1);
                    part += __shfl_xor_sync(0xFFFFFFFFu, part, 2);
                    if ((lane & 3) == 0) red[wc * 128 + r] = part;
                } else {
                    #pragma unroll
                    for (int nb = 0; nb < 8; nb++)
                        *(float2*)(crow + nb * 8) =
                            make_float2(acc[m][nb][cp], acc[m][nb][cp + 1]);
                }
            }
        }
        __syncthreads();    // publishes staged A buf, red for scores
        if (FUSE && tid < 128) {
            long g2 = (long)tile * 128 + tid;
            scores[g2] = (red[tid] + red[128 + tid]) * tcl[g2] * lwv;
        }
        cur ^= 1; rcur ^= 1;
    }
}

// ---------------------------------------------------------------------------
// Scatter-add: axw[dst] += xw[src]  (warp per edge, vector reduction)
// ---------------------------------------------------------------------------
__global__ void scatter_kernel(const void* __restrict__ eidx,
                               const float* __restrict__ xw,
                               float* __restrict__ axw) {
    long t = (long)blockIdx.x * blockDim.x + threadIdx.x;
    if (t >= (long)E_EDGES * 32) return;
    long e = t >> 5;
    int  q = (int)(t & 31) * 4;
    long src = ld_idx(eidx, e);
    long dst = ld_idx(eidx, (long)E_EDGES + e);
    float4 v = *(const float4*)&xw[src * 128 + q];
    float* o = &axw[dst * 128 + q];
    asm volatile("red.global.add.v4.f32 [%0], {%1, %2, %3, %4};"
                 :: "l"(o), "f"(v.x), "f"(v.y), "f"(v.z), "f"(v.w) : "memory");
}

// ---------------------------------------------------------------------------
// Launch
// ---------------------------------------------------------------------------
extern "C" void kernel_launch(void* const* d_in, const int* in_sizes, int n_in,
                              void* d_out, int out_size) {
    const float* x    = (const float*)d_in[0];   // [N, 256]
    const float* ea   = (const float*)d_in[1];   // [E, 128]
    const float* tc   = (const float*)d_in[2];   // [E]
    const float* wn   = (const float*)d_in[3];   // [256, 128]
    const float* we   = (const float*)d_in[4];   // [128, 128]
    const float* lw   = (const float*)d_in[5];   // [1]
    const void*  eidx = d_in[6];                 // [2, E] int32 or int64

    float* out    = (float*)d_out;
    float* axw    = out;                               // [N, 128]
    float* ew     = out + (long)N_NODES * 128;         // [E, 128]
    float* scores = ew + (long)E_EDGES * 128;          // [E]

    float* xw;
    cudaGetSymbolAddress((void**)&xw, g_xw);

    const int SMEM_XW = 256 * 512 + 65536 + 2048;   // 198656
    const int SMEM_EW = 128 * 512 + 65536 + 2048;   // 133120
    cudaFuncSetAttribute(gemm_kernel<2, false>,
                         cudaFuncAttributeMaxDynamicSharedMemorySize, SMEM_XW);
    cudaFuncSetAttribute(gemm_kernel<1, true>,
                         cudaFuncAttributeMaxDynamicSharedMemorySize, SMEM_EW);

    // 1) dtype detection
    detect_idx_kernel<<<1, 32>>>(eidx);

    // 2) zero axw (accumulated via reductions)
    {
        int n4 = N_NODES * 128 / 4;
        zero4_kernel<<<(n4 + 255) / 256, 256>>>((float4*)axw, n4);
    }

    // 3) xw = x @ Wn  (fp16 2-pass HMMA, K=256)
    gemm_kernel<2, false><<<152, 256, SMEM_XW>>>(
        x, wn, xw, N_NODES, nullptr, nullptr, nullptr, nullptr, nullptr);

    // 4) axw = segment_sum(xw[src], dst)
    {
        long total = (long)E_EDGES * 32;
        scatter_kernel<<<(int)((total + 255) / 256), 256>>>(eidx, xw, axw);
    }

    // 5) ew = edge_attr @ We + fused DistMult scores (fp16 2-pass, K=128)
    gemm_kernel<1, true><<<152, 256, SMEM_EW>>>(
        ea, we, ew, E_EDGES, eidx, axw, tc, lw, scores);
}

// round 6
// speedup vs baseline: 2.5839x; 1.0124x over previous
#include <cuda_runtime.h>
#include <cuda_fp16.h>
#include <cstdint>

#define N_NODES 100000
#define E_EDGES 640000

// ---------------------------------------------------------------------------
// Global scratch
// ---------------------------------------------------------------------------
__device__ float g_xw[(size_t)N_NODES * 128];   // x @ Wn
__device__ int   g_idx64;                        // edge_index dtype flag

// ---------------------------------------------------------------------------
// Helpers
// ---------------------------------------------------------------------------
__device__ __forceinline__ uint32_t smem_u32(const void* p) {
    uint32_t a;
    asm("{ .reg .u64 t; cvta.to.shared.u64 t, %1; cvt.u32.u64 %0, t; }"
        : "=r"(a) : "l"(p));
    return a;
}

__device__ __forceinline__ void mma_f16(float* d, const uint32_t* a, const uint32_t* b) {
    asm volatile(
        "mma.sync.aligned.m16n8k16.row.col.f32.f16.f16.f32 "
        "{%0,%1,%2,%3}, {%4,%5,%6,%7}, {%8,%9}, {%0,%1,%2,%3};"
        : "+f"(d[0]), "+f"(d[1]), "+f"(d[2]), "+f"(d[3])
        : "r"(a[0]), "r"(a[1]), "r"(a[2]), "r"(a[3]), "r"(b[0]), "r"(b[1]));
}

__device__ __forceinline__ void ldsm_x4(uint32_t* r, uint32_t addr) {
    asm volatile("ldmatrix.sync.aligned.m8n8.x4.shared.b16 {%0,%1,%2,%3}, [%4];"
                 : "=r"(r[0]), "=r"(r[1]), "=r"(r[2]), "=r"(r[3]) : "r"(addr));
}
__device__ __forceinline__ void ldsm_x4t(uint32_t* r, uint32_t addr) {
    asm volatile("ldmatrix.sync.aligned.m8n8.x4.trans.shared.b16 {%0,%1,%2,%3}, [%4];"
                 : "=r"(r[0]), "=r"(r[1]), "=r"(r[2]), "=r"(r[3]) : "r"(addr));
}

__device__ __forceinline__ void prefetch_l2(const void* p) {
    asm volatile("prefetch.global.L2 [%0];" :: "l"(p));
}

// ---------------------------------------------------------------------------
// edge_index dtype detection (int32 vs int64)
// ---------------------------------------------------------------------------
__global__ void detect_idx_kernel(const void* __restrict__ eidx) {
    if (threadIdx.x == 0 && blockIdx.x == 0) {
        const unsigned long long* p = (const unsigned long long*)eidx;
        int ok = 1;
        #pragma unroll 1
        for (int i = 0; i < 64; i++)
            if (p[i] >= (unsigned long long)N_NODES) { ok = 0; break; }
        g_idx64 = ok;
    }
}

__device__ __forceinline__ long ld_idx(const void* __restrict__ p, long i) {
    if (g_idx64) return (long)((const long long*)p)[i];
    return (long)((const int*)p)[i];
}

__global__ void zero4_kernel(float4* __restrict__ p, int n4) {
    int i = blockIdx.x * blockDim.x + threadIdx.x;
    if (i < n4) p[i] = make_float4(0.f, 0.f, 0.f, 0.f);
}

// ---------------------------------------------------------------------------
// Unified persistent GEMM: C[M x 128] = A[M x K] @ W[K x 128], K = KCH*128.
// A -> fp16 (single). WPASS==2: W -> fp16 hi + lo (2 MMA passes).
// WPASS==1: W -> single fp16 (1 MMA pass; ~2x faster, err ~5e-4 rel).
// Cross-chunk A double-buffering, 1 __syncthreads per 128-k chunk.
// FUSE: DistMult scores from accumulator fragments in the epilogue, with
// L2 prefetch of the gather rows issued before the MMA loop.
//
// Smem layout:
//   [0, K*256)              W hi  (fp16, swizzled, k-row stride 256B)
//   [K*256, K*512)          W lo  (only if WPASS==2)
//   [K*256*WPASS, +65536)   A chunk bufs: 2 x 32768 (128x128 fp16)
//   [.. +2KB)               score reduction bufs (2 x 1KB)
// ---------------------------------------------------------------------------
template<int KCH, bool FUSE, int WPASS>
__global__ __launch_bounds__(256, 1)
void gemm_kernel(const float* __restrict__ A, const float* __restrict__ W,
                 float* __restrict__ C, int M,
                 const void* __restrict__ eidx,
                 const float* __restrict__ axw,
                 const float* __restrict__ tcl,
                 const float* __restrict__ lw,
                 float* __restrict__ scores) {
    constexpr int K = KCH * 128;
    constexpr uint32_t OFF_WLO = (uint32_t)K * 256;
    constexpr uint32_t OFF_A   = (uint32_t)K * 256 * WPASS;
    constexpr uint32_t OFF_RED = OFF_A + 65536;

    extern __shared__ __align__(128) char smem[];
    const uint32_t sb = smem_u32(smem);
    const int tid = threadIdx.x, lane = tid & 31, wid = tid >> 5;
    const int wr = wid & 3, wc = wid >> 2;

    // ---- W load (+ optional fp16 hi/lo split) into swizzled smem (once) ----
    for (int p = tid; p < K * 64; p += 256) {
        int k = p >> 6, n = (p & 63) * 2;
        float2 wv = *(const float2*)(W + (long)k * 128 + n);
        __half2 hp = __floats2half2_rn(wv.x, wv.y);
        uint32_t off = (uint32_t)k * 256 +
                       ((((uint32_t)n >> 3) ^ ((uint32_t)k & 7)) << 4) + ((n & 7) << 1);
        *(__half2*)(smem + off) = hp;
        if (WPASS == 2) {
            __half2 lp = __floats2half2_rn(wv.x - __low2float(hp),
                                           wv.y - __high2float(hp));
            *(__half2*)(smem + OFF_WLO + off) = lp;
        }
    }

    const float lwv = FUSE ? lw[0] : 0.f;
    const int ntiles = (M + 127) >> 7;
    const int G = gridDim.x;
    float2 pref[32];

    auto prefetch = [&](int t, int kc) {
        #pragma unroll
        for (int i = 0; i < 32; i++) {
            int p = i * 256 + tid;
            int r = p >> 6, pc = p & 63;
            long row = (long)t * 128 + r;
            float2 v = make_float2(0.f, 0.f);
            if (row < M) v = __ldcs((const float2*)(A + row * (long)K + kc * 128 + pc * 2));
            pref[i] = v;
        }
    };
    auto store_buf = [&](int b) {
        #pragma unroll
        for (int i = 0; i < 32; i++) {
            int p = i * 256 + tid;
            int r = p >> 6, col = (p & 63) * 2;
            __half2 hp = __floats2half2_rn(pref[i].x, pref[i].y);
            uint32_t off = (uint32_t)r * 256 +
                           ((((uint32_t)col >> 3) ^ ((uint32_t)r & 7)) << 4) +
                           ((col & 7) << 1);
            *(__half2*)(smem + OFF_A + (uint32_t)b * 32768 + off) = hp;
        }
    };

    int tile = blockIdx.x;
    if (tile < ntiles) {
        prefetch(tile, 0);
        store_buf(0);
        int nt = tile, nkc = 1;
        if (KCH == 1) { nt = tile + G; nkc = 0; }
        if (nt < ntiles) prefetch(nt, nkc);
    }
    __syncthreads();

    int cur = 0, rcur = 0;
    for (; tile < ntiles; tile += G) {
        float acc[2][8][4];
        #pragma unroll
        for (int m = 0; m < 2; m++)
            #pragma unroll
            for (int nb = 0; nb < 8; nb++)
                #pragma unroll
                for (int c = 0; c < 4; c++) acc[m][nb][c] = 0.f;

        const int r0 = wr * 32 + (lane >> 2);
        int isrc[4], idst[4];
        if (FUSE) {
            #pragma unroll
            for (int j = 0; j < 4; j++) {
                long grow = (long)tile * 128 + r0 + j * 8;
                isrc[j] = (int)ld_idx(eidx, grow);
                idst[j] = (int)ld_idx(eidx, (long)E_EDGES + grow);
            }
            // warm L2 for the epilogue gathers (2 lines per 256B row-half)
            #pragma unroll
            for (int j = 0; j < 4; j++) {
                const float* hq = axw + (long)isrc[j] * 128 + wc * 64;
                const float* tq = axw + (long)idst[j] * 128 + wc * 64;
                prefetch_l2(hq); prefetch_l2(hq + 32);
                prefetch_l2(tq); prefetch_l2(tq + 32);
            }
        }

        for (int kc = 0; kc < KCH; kc++) {
            // regs hold the successor chunk of (tile, kc): stage it
            int nt1 = tile, nkc1 = kc + 1;
            if (nkc1 == KCH) { nkc1 = 0; nt1 = tile + G; }
            if (nt1 < ntiles) store_buf(cur ^ 1);
            int nt2 = nt1, nkc2 = nkc1 + 1;
            if (nkc2 == KCH) { nkc2 = 0; nt2 = nt1 + G; }
            if (nt2 < ntiles) prefetch(nt2, nkc2);

            const uint32_t abase = sb + OFF_A + (uint32_t)cur * 32768;
            #pragma unroll
            for (int s = 0; s < 8; s++) {
                uint32_t a[2][4];
                #pragma unroll
                for (int m = 0; m < 2; m++) {
                    uint32_t r = (uint32_t)(wr * 32 + m * 16 + (lane & 15));
                    uint32_t ch = (uint32_t)(s * 2 + (lane >> 4));
                    ldsm_x4(a[m], abase + r * 256 + (((ch ^ (r & 7)) << 4)));
                }
                uint32_t bh[4][4], bl[4][4];
                #pragma unroll
                for (int p4 = 0; p4 < 4; p4++) {
                    uint32_t k = (uint32_t)(kc * 128 + s * 16 + (lane & 15));
                    uint32_t nch = (uint32_t)(wc * 8 + p4 * 2 + (lane >> 4));
                    uint32_t off = k * 256 + (((nch ^ (k & 7)) << 4));
                    ldsm_x4t(bh[p4], sb + off);
                    if (WPASS == 2) ldsm_x4t(bl[p4], sb + OFF_WLO + off);
                }
                #pragma unroll
                for (int m = 0; m < 2; m++)
                    #pragma unroll
                    for (int p4 = 0; p4 < 4; p4++)
                        #pragma unroll
                        for (int h = 0; h < 2; h++) {
                            float* d = acc[m][p4 * 2 + h];
                            mma_f16(d, a[m], &bh[p4][2 * h]);
                            if (WPASS == 2) mma_f16(d, a[m], &bl[p4][2 * h]);
                        }
            }
            if (kc < KCH - 1) { __syncthreads(); cur ^= 1; }
        }

        // ---- epilogue: C store (+ fused DistMult partials) ----
        float* red = (float*)(smem + OFF_RED + (uint32_t)rcur * 1024);
        #pragma unroll
        for (int j = 0; j < 4; j++) {
            const int m = j >> 1, cp = (j & 1) * 2;
            const int r = r0 + j * 8;
            long grow = (long)tile * 128 + r;
            if (grow < M) {
                float* crow = C + grow * 128 + wc * 64 + (lane & 3) * 2;
                if (FUSE) {
                    const float* hq = axw + (long)isrc[j] * 128 + wc * 64 + (lane & 3) * 2;
                    const float* tq = axw + (long)idst[j] * 128 + wc * 64 + (lane & 3) * 2;
                    float part = 0.f;
                    #pragma unroll
                    for (int nb = 0; nb < 8; nb++) {
                        float2 v = make_float2(acc[m][nb][cp], acc[m][nb][cp + 1]);
                        __stcs((float2*)(crow + nb * 8), v);
                        float2 h2 = *(const float2*)(hq + nb * 8);
                        float2 t2 = *(const float2*)(tq + nb * 8);
                        part = fmaf(v.x * h2.x, t2.x, part);
                        part = fmaf(v.y * h2.y, t2.y, part);
                    }
                    part += __shfl_xor_sync(0xFFFFFFFFu, part, 1);
                    part += __shfl_xor_sync(0xFFFFFFFFu, part, 2);
                    if ((lane & 3) == 0) red[wc * 128 + r] = part;
                } else {
                    #pragma unroll
                    for (int nb = 0; nb < 8; nb++)
                        *(float2*)(crow + nb * 8) =
                            make_float2(acc[m][nb][cp], acc[m][nb][cp + 1]);
                }
            }
        }
        __syncthreads();    // publishes staged A buf, red for scores
        if (FUSE && tid < 128) {
            long g2 = (long)tile * 128 + tid;
            scores[g2] = (red[tid] + red[128 + tid]) * tcl[g2] * lwv;
        }
        cur ^= 1; rcur ^= 1;
    }
}

// ---------------------------------------------------------------------------
// Scatter-add: axw[dst] += xw[src]  (warp per edge, vector reduction)
// ---------------------------------------------------------------------------
__global__ void scatter_kernel(const void* __restrict__ eidx,
                               const float* __restrict__ xw,
                               float* __restrict__ axw) {
    long t = (long)blockIdx.x * blockDim.x + threadIdx.x;
    if (t >= (long)E_EDGES * 32) return;
    long e = t >> 5;
    int  q = (int)(t & 31) * 4;
    long src = ld_idx(eidx, e);
    long dst = ld_idx(eidx, (long)E_EDGES + e);
    float4 v = *(const float4*)&xw[src * 128 + q];
    float* o = &axw[dst * 128 + q];
    asm volatile("red.global.add.v4.f32 [%0], {%1, %2, %3, %4};"
                 :: "l"(o), "f"(v.x), "f"(v.y), "f"(v.z), "f"(v.w) : "memory");
}

// ---------------------------------------------------------------------------
// Launch
// ---------------------------------------------------------------------------
extern "C" void kernel_launch(void* const* d_in, const int* in_sizes, int n_in,
                              void* d_out, int out_size) {
    const float* x    = (const float*)d_in[0];   // [N, 256]
    const float* ea   = (const float*)d_in[1];   // [E, 128]
    const float* tc   = (const float*)d_in[2];   // [E]
    const float* wn   = (const float*)d_in[3];   // [256, 128]
    const float* we   = (const float*)d_in[4];   // [128, 128]
    const float* lw   = (const float*)d_in[5];   // [1]
    const void*  eidx = d_in[6];                 // [2, E] int32 or int64

    float* out    = (float*)d_out;
    float* axw    = out;                               // [N, 128]
    float* ew     = out + (long)N_NODES * 128;         // [E, 128]
    float* scores = ew + (long)E_EDGES * 128;          // [E]

    float* xw;
    cudaGetSymbolAddress((void**)&xw, g_xw);

    const int SMEM_XW = 256 * 512 + 65536 + 2048;   // 198656 (W hi+lo, K=256)
    const int SMEM_EW = 128 * 256 + 65536 + 2048;   // 100352 (W hi only, K=128)
    cudaFuncSetAttribute(gemm_kernel<2, false, 2>,
                         cudaFuncAttributeMaxDynamicSharedMemorySize, SMEM_XW);
    cudaFuncSetAttribute(gemm_kernel<1, true, 1>,
                         cudaFuncAttributeMaxDynamicSharedMemorySize, SMEM_EW);

    // 1) dtype detection
    detect_idx_kernel<<<1, 32>>>(eidx);

    // 2) zero axw (accumulated via reductions)
    {
        int n4 = N_NODES * 128 / 4;
        zero4_kernel<<<(n4 + 255) / 256, 256>>>((float4*)axw, n4);
    }

    // 3) xw = x @ Wn  (fp16 2-pass HMMA, K=256 — protects axw precision)
    gemm_kernel<2, false, 2><<<152, 256, SMEM_XW>>>(
        x, wn, xw, N_NODES, nullptr, nullptr, nullptr, nullptr, nullptr);

    // 4) axw = segment_sum(xw[src], dst)
    {
        long total = (long)E_EDGES * 32;
        scatter_kernel<<<(int)((total + 255) / 256), 256>>>(eidx, xw, axw);
    }

    // 5) ew = edge_attr @ We + fused DistMult scores (fp16 1-pass, K=128)
    gemm_kernel<1, true, 1><<<152, 256, SMEM_EW>>>(
        ea, we, ew, E_EDGES, eidx, axw, tc, lw, scores);
}